// round 8
// baseline (speedup 1.0000x reference)
#include <cuda_runtime.h>
#include <math.h>
#include <stdint.h>

#define NROWS 8192      // B*T
#define HD    640
#define NP    230
#define NM    96
#define TM    64        // rows per CTA
#define KC    32        // k per chunk
#define NCHUNK (HD / KC)  // 20
#define A_PAD 36
#define P_PAD 258
#define M_PAD 97
#define MAXINV 32
#define NTHREADS 512

#define A_BYTES 9216    // 64*36*4
#define B_BYTES 32768   // 8192 floats

// ---- smem byte offsets ----
#define SM_A0    0                        // 2 x 9216  = 18432
#define SM_B0    18432                    // 2 x 32768 -> 83968
// epilogue aliases GEMM region:
#define SM_PHONE 0                        // 64*258*4 = 66048
#define SM_PH    66048                    // 64*97*4  = 24832 -> 90880
// persistent tables:
#define SM_TBL   90880                    // icnt 96*4 -> 91264
#define SM_ILIST 91264                    // 96*32    -> 94336
#define SM_MAXV  94336                    // 64*4
#define SM_LSEV  94592                    // 64*4
#define SM_MB    94848                    // 2 mbarriers (16B)
#define SM_TOTAL 94880

__device__ float         g_Bp[NCHUNK * 8192];   // fragment-permuted B (tf32-rounded)
__device__ int           g_icnt[NM];
__device__ unsigned char g_ilist[NM * MAXINV];

// ---------------- helpers ----------------
__device__ __forceinline__ uint32_t smem_u32(const void* p) {
    uint32_t a;
    asm("{ .reg .u64 t; cvta.to.shared.u64 t, %1; cvt.u32.u64 %0, t; }" : "=r"(a) : "l"(p));
    return a;
}
__device__ __forceinline__ void cp16(uint32_t dst, const void* src) {
    asm volatile("cp.async.cg.shared.global [%0], [%1], 16;" :: "r"(dst), "l"(src));
}
#define CP_COMMIT() asm volatile("cp.async.commit_group;" ::: "memory")
#define CP_WAIT(N)  asm volatile("cp.async.wait_group %0;" :: "n"(N) : "memory")

__device__ __forceinline__ void bulk_g2s(uint32_t dst, const void* src, uint32_t bytes,
                                         uint32_t mbar) {
    asm volatile(
        "cp.async.bulk.shared::cta.global.mbarrier::complete_tx::bytes [%0], [%1], %2, [%3];"
        :: "r"(dst), "l"(src), "r"(bytes), "r"(mbar) : "memory");
}
#define MBAR_INIT(mb, c) \
    asm volatile("mbarrier.init.shared.b64 [%0], %1;" :: "r"((uint32_t)(mb)), "r"((uint32_t)(c)) : "memory")
#define MBAR_EXPECT(mb, tx) \
    asm volatile("mbarrier.arrive.expect_tx.shared.b64 _, [%0], %1;" \
                 :: "r"((uint32_t)(mb)), "r"((uint32_t)(tx)) : "memory")
__device__ __forceinline__ void mbar_wait(uint32_t mb, uint32_t parity) {
    asm volatile(
        "{ .reg .pred P1;\n\t"
        "WL_%=: mbarrier.try_wait.parity.acquire.cta.shared::cta.b64 P1, [%0], %1, 0x989680;\n\t"
        "@P1 bra.uni WD_%=;\n\t"
        "bra.uni WL_%=;\n\t"
        "WD_%=: }" :: "r"(mb), "r"(parity) : "memory");
}

// m16n8k8 tf32 MMA, D += A*B
__device__ __forceinline__ void mma_tf32(float* d, const uint32_t* a, uint32_t b0, uint32_t b1) {
    asm volatile(
        "mma.sync.aligned.m16n8k8.row.col.f32.tf32.tf32.f32 "
        "{%0,%1,%2,%3}, {%4,%5,%6,%7}, {%8,%9}, {%0,%1,%2,%3};"
        : "+f"(d[0]), "+f"(d[1]), "+f"(d[2]), "+f"(d[3])
        : "r"(a[0]), "r"(a[1]), "r"(a[2]), "r"(a[3]), "r"(b0), "r"(b1));
}

// ---------------- prologue kernel ----------------
// blocks 0..19: pack one 32-row chunk of B into fragment order via coalesced smem staging.
// blocks 20..31: inverse map, ONE phoneme per warp, rounds prefetched (MLP=8).
__global__ void prep_kernel(const float* __restrict__ f2p,
                            const float* __restrict__ mapping) {
    __shared__ float s[32 * 232];
    const int tid = threadIdx.x;
    const int b   = blockIdx.x;
    if (b < NCHUNK) {
        const float* src = f2p + (size_t)b * KC * NP;
        for (int idx = tid; idx < KC * NP; idx += 256) {
            int rr = idx / NP, c = idx - rr * NP;
            s[rr * 232 + c] = src[idx];
        }
        __syncthreads();
        float* dst = g_Bp + (size_t)b * 8192;
        for (int rem = tid; rem < 8192; rem += 256) {
            int nt   = rem >> 8;
            int r2   = rem & 255;
            int ks   = r2 >> 6;
            int lane = (r2 >> 1) & 31;
            int i    = r2 & 1;
            int n  = nt * 8 + (lane >> 2);
            int kk = ks * 8 + (lane & 3) + 4 * i;
            float v = (n < NP) ? s[kk * 232 + n] : 0.0f;
            uint32_t t;
            asm("cvt.rna.tf32.f32 %0, %1;" : "=r"(t) : "f"(v));
            dst[rem] = __uint_as_float(t);
        }
    } else {
        int wid  = tid >> 5;
        int lane = tid & 31;
        int m = (b - NCHUNK) * 8 + wid;   // 0..95, one phoneme per warp
        bool hit[8];
        #pragma unroll
        for (int rr = 0; rr < 8; rr++) {
            int p = rr * 32 + lane;
            hit[rr] = (p < NP) && (mapping[m * NP + p] > 0.0f);  // 8 independent loads
        }
        int cnt = 0;
        #pragma unroll
        for (int rr = 0; rr < 8; rr++) {
            unsigned bal = __ballot_sync(0xffffffffu, hit[rr]);
            if (hit[rr]) {
                int pos = cnt + __popc(bal & ((1u << lane) - 1u));
                if (pos < MAXINV) g_ilist[m * MAXINV + pos] = (unsigned char)(rr * 32 + lane);
            }
            cnt += __popc(bal);
        }
        if (lane == 0) g_icnt[m] = (cnt < MAXINV) ? cnt : MAXINV;
    }
}

// ---------------- main kernel ----------------
__global__ __launch_bounds__(NTHREADS, 1)
void phon_mma_kernel(const float* __restrict__ enc, float* __restrict__ out) {
    extern __shared__ char smem[];
    const uint32_t sbase = smem_u32(smem);
    const int tid  = threadIdx.x;
    const int wid  = tid >> 5;
    const int lane = tid & 31;
    const int wm   = wid >> 3;   // 0..1  (M half)
    const int wn   = wid & 7;    // 0..7  (32-col slice)
    const int row0 = blockIdx.x * TM;

    int*           sicnt  = (int*)(smem + SM_TBL);
    unsigned char* silist = (unsigned char*)(smem + SM_ILIST);
    float*         sMaxv  = (float*)(smem + SM_MAXV);
    float*         sLsev  = (float*)(smem + SM_LSEV);

    // mbarriers + tables
    if (tid == 0) { MBAR_INIT(sbase + SM_MB, 1); MBAR_INIT(sbase + SM_MB + 8, 1); }
    if (tid < NM) sicnt[tid] = g_icnt[tid];
    for (int i = tid; i < NM * MAXINV; i += NTHREADS) silist[i] = g_ilist[i];
    __syncthreads();   // mbarrier init visible before any wait

    float acc[2][4][4];
    #pragma unroll
    for (int i = 0; i < 2; i++)
        #pragma unroll
        for (int j = 0; j < 4; j++)
            #pragma unroll
            for (int c = 0; c < 4; c++) acc[i][j][c] = 0.0f;

    auto issue_a = [&](int kc, int buf) {
        int r = tid >> 3, g = tid & 7;   // 512 float4, one per thread
        cp16(sbase + SM_A0 + buf * A_BYTES + (uint32_t)(r * A_PAD + g * 4) * 4,
             enc + (size_t)(row0 + r) * HD + kc * KC + g * 4);
    };
    auto issue_b = [&](int kc, int buf) {
        if (tid == 0) {
            uint32_t mb = sbase + SM_MB + buf * 8;
            MBAR_EXPECT(mb, B_BYTES);
            bulk_g2s(sbase + SM_B0 + buf * B_BYTES, g_Bp + (size_t)kc * 8192, B_BYTES, mb);
        }
    };

    auto do_chunk = [&](int buf) {
        const float* sA = (const float*)(smem + SM_A0 + buf * A_BYTES);
        const char*  sB = smem + SM_B0 + buf * B_BYTES;
        #pragma unroll
        for (int ks = 0; ks < 4; ks++) {
            uint32_t afr[2][4];
            #pragma unroll
            for (int i = 0; i < 2; i++) {
                const float* ap = sA + (wm * 32 + i * 16 + (lane >> 2)) * A_PAD
                                     + ks * 8 + (lane & 3);
                afr[i][0] = __float_as_uint(ap[0]);
                afr[i][1] = __float_as_uint(ap[8 * A_PAD]);
                afr[i][2] = __float_as_uint(ap[4]);
                afr[i][3] = __float_as_uint(ap[8 * A_PAD + 4]);
            }
            float2 bfr[4];
            #pragma unroll
            for (int j = 0; j < 4; j++) {
                int nt = wn * 4 + j;
                bfr[j] = *(const float2*)(sB + ((nt * 4 + ks) * 32 + lane) * 8);
            }
            #pragma unroll
            for (int i = 0; i < 2; i++)
                #pragma unroll
                for (int j = 0; j < 4; j++)
                    mma_tf32(acc[i][j], afr[i],
                             __float_as_uint(bfr[j].x), __float_as_uint(bfr[j].y));
        }
    };

    issue_a(0, 0); CP_COMMIT();
    issue_b(0, 0);
    uint32_t par[2] = {0, 0};

    #pragma unroll 1
    for (int kc = 0; kc < NCHUNK; kc++) {
        const int buf = kc & 1;
        if (kc + 1 < NCHUNK) {
            issue_a(kc + 1, buf ^ 1); CP_COMMIT();
            issue_b(kc + 1, buf ^ 1);
            CP_WAIT(1);
        } else {
            CP_WAIT(0);
        }
        mbar_wait(sbase + SM_MB + buf * 8, par[buf]); par[buf] ^= 1;
        __syncthreads();
        do_chunk(buf);
        __syncthreads();
    }

    // ---- epilogue ----
    const float scale = 0.039528470752104741f;  // 1/sqrt(640)
    float* sPhone = (float*)(smem + SM_PHONE);
    float* sPh    = (float*)(smem + SM_PH);

    #pragma unroll
    for (int i = 0; i < 2; i++) {
        int r = wm * 32 + i * 16 + (lane >> 2);
        #pragma unroll
        for (int j = 0; j < 4; j++) {
            int c = wn * 32 + j * 8 + (lane & 3) * 2;
            float2 v0 = make_float2(acc[i][j][0] * scale, acc[i][j][1] * scale);
            float2 v1 = make_float2(acc[i][j][2] * scale, acc[i][j][3] * scale);
            *(float2*)(sPhone + r * P_PAD + c)       = v0;
            *(float2*)(sPhone + (r + 8) * P_PAD + c) = v1;
        }
    }
    __syncthreads();

    // gather-max via inverse map: 64 rows x 96 phonemes
    for (int idx = tid; idx < TM * NM; idx += NTHREADS) {
        int r = idx / NM;
        int m = idx - r * NM;
        int cnt = sicnt[m];
        const unsigned char* lst = silist + m * MAXINV;
        float mx = -INFINITY;
        for (int c = 0; c < cnt; c++)
            mx = fmaxf(mx, sPhone[r * P_PAD + lst[c]]);
        sPh[r * M_PAD + m] = mx;
    }
    __syncthreads();

    // per-row max + logsumexp: 4 threads per row (first 256 threads)
    if (tid < 256) {
        int r = tid >> 2;
        int q = tid & 3;
        const float* row = sPh + r * M_PAD;
        float mx = -INFINITY;
        #pragma unroll
        for (int m = q * 24; m < q * 24 + 24; m++) mx = fmaxf(mx, row[m]);
        mx = fmaxf(mx, __shfl_xor_sync(0xffffffffu, mx, 1));
        mx = fmaxf(mx, __shfl_xor_sync(0xffffffffu, mx, 2));
        float s = 0.0f;
        #pragma unroll
        for (int m = q * 24; m < q * 24 + 24; m++) s += expf(row[m] - mx);
        s += __shfl_xor_sync(0xffffffffu, s, 1);
        s += __shfl_xor_sync(0xffffffffu, s, 2);
        if (q == 0) { sMaxv[r] = mx; sLsev[r] = logf(s); }
    }
    __syncthreads();

    // coalesced output
    for (int idx = tid; idx < TM * NM; idx += NTHREADS) {
        int r = idx / NM;
        int m = idx - r * NM;
        out[(size_t)(row0 + r) * NM + m] = sPh[r * M_PAD + m] - sMaxv[r] - sLsev[r];
    }
}

extern "C" void kernel_launch(void* const* d_in, const int* in_sizes, int n_in,
                              void* d_out, int out_size) {
    const float* enc     = (const float*)d_in[0];
    const float* f2p     = (const float*)d_in[1];
    const float* mapping = (const float*)d_in[2];
    float*       out     = (float*)d_out;

    cudaFuncSetAttribute(phon_mma_kernel,
                         cudaFuncAttributeMaxDynamicSharedMemorySize, SM_TOTAL);

    prep_kernel<<<NCHUNK + 12, 256>>>(f2p, mapping);
    phon_mma_kernel<<<NROWS / TM, NTHREADS, SM_TOTAL>>>(enc, out);
}

// round 9
// speedup vs baseline: 1.4605x; 1.4605x over previous
#include <cuda_runtime.h>
#include <math.h>
#include <stdint.h>

#define NROWS 8192      // B*T
#define HD    640
#define NP    230
#define NM    96
#define TM    64        // rows per CTA
#define KC    32        // k per chunk
#define NCHUNK (HD / KC)  // 20
#define A_PAD 36
#define P_PAD 258
#define M_PAD 97
#define MAXINV 32
#define NTHREADS 1024

#define A_BYTES 9216    // 64*36*4
#define B_BYTES 32768   // 8192 floats

// ---- smem byte offsets ----
#define SM_A0    0                        // 2 x 9216  = 18432
#define SM_B0    18432                    // 2 x 32768 -> 83968
// epilogue aliases GEMM region:
#define SM_PHONE 0                        // 64*258*4 = 66048
#define SM_PH    66048                    // 64*97*4  = 24832 -> 90880
// persistent tables:
#define SM_TBL   90880                    // icnt 96*4 -> 91264
#define SM_ILIST 91264                    // 96*32    -> 94336
#define SM_MAXV  94336                    // 64*4
#define SM_LSEV  94592                    // 64*4
#define SM_TOTAL 94848

__device__ float         g_Bp[NCHUNK * 8192];   // fragment-permuted B (tf32-rounded)
__device__ int           g_icnt[NM];
__device__ unsigned char g_ilist[NM * MAXINV];

// ---------------- helpers ----------------
__device__ __forceinline__ uint32_t smem_u32(const void* p) {
    uint32_t a;
    asm("{ .reg .u64 t; cvta.to.shared.u64 t, %1; cvt.u32.u64 %0, t; }" : "=r"(a) : "l"(p));
    return a;
}
__device__ __forceinline__ void cp16(uint32_t dst, const void* src) {
    asm volatile("cp.async.cg.shared.global [%0], [%1], 16;" :: "r"(dst), "l"(src));
}
#define CP_COMMIT() asm volatile("cp.async.commit_group;" ::: "memory")
#define CP_WAIT(N)  asm volatile("cp.async.wait_group %0;" :: "n"(N) : "memory")

// m16n8k8 tf32 MMA, D += A*B
__device__ __forceinline__ void mma_tf32(float* d, const uint32_t* a, uint32_t b0, uint32_t b1) {
    asm volatile(
        "mma.sync.aligned.m16n8k8.row.col.f32.tf32.tf32.f32 "
        "{%0,%1,%2,%3}, {%4,%5,%6,%7}, {%8,%9}, {%0,%1,%2,%3};"
        : "+f"(d[0]), "+f"(d[1]), "+f"(d[2]), "+f"(d[3])
        : "r"(a[0]), "r"(a[1]), "r"(a[2]), "r"(a[3]), "r"(b0), "r"(b1));
}

// ---------------- prologue kernel ----------------
// blocks 0..19: pack one 32-row chunk of B into fragment order via coalesced smem staging.
// blocks 20..31: inverse map, ONE phoneme per warp, rounds prefetched (MLP=8).
__global__ void prep_kernel(const float* __restrict__ f2p,
                            const float* __restrict__ mapping) {
    __shared__ float s[32 * 232];
    const int tid = threadIdx.x;
    const int b   = blockIdx.x;
    if (b < NCHUNK) {
        const float* src = f2p + (size_t)b * KC * NP;
        for (int idx = tid; idx < KC * NP; idx += 256) {
            int rr = idx / NP, c = idx - rr * NP;
            s[rr * 232 + c] = src[idx];
        }
        __syncthreads();
        float* dst = g_Bp + (size_t)b * 8192;
        for (int rem = tid; rem < 8192; rem += 256) {
            int nt   = rem >> 8;
            int r2   = rem & 255;
            int ks   = r2 >> 6;
            int lane = (r2 >> 1) & 31;
            int i    = r2 & 1;
            int n  = nt * 8 + (lane >> 2);
            int kk = ks * 8 + (lane & 3) + 4 * i;
            float v = (n < NP) ? s[kk * 232 + n] : 0.0f;
            uint32_t t;
            asm("cvt.rna.tf32.f32 %0, %1;" : "=r"(t) : "f"(v));
            dst[rem] = __uint_as_float(t);
        }
    } else {
        int wid  = tid >> 5;
        int lane = tid & 31;
        int m = (b - NCHUNK) * 8 + wid;   // 0..95, one phoneme per warp
        bool hit[8];
        #pragma unroll
        for (int rr = 0; rr < 8; rr++) {
            int p = rr * 32 + lane;
            hit[rr] = (p < NP) && (mapping[m * NP + p] > 0.0f);  // independent loads
        }
        int cnt = 0;
        #pragma unroll
        for (int rr = 0; rr < 8; rr++) {
            unsigned bal = __ballot_sync(0xffffffffu, hit[rr]);
            if (hit[rr]) {
                int pos = cnt + __popc(bal & ((1u << lane) - 1u));
                if (pos < MAXINV) g_ilist[m * MAXINV + pos] = (unsigned char)(rr * 32 + lane);
            }
            cnt += __popc(bal);
        }
        if (lane == 0) g_icnt[m] = (cnt < MAXINV) ? cnt : MAXINV;
    }
}

// ---------------- main kernel ----------------
// 1024 threads = 32 warps in a 4 x 8 grid; warp tile 16 x 32.
__global__ __launch_bounds__(NTHREADS, 1)
void phon_mma_kernel(const float* __restrict__ enc, float* __restrict__ out) {
    extern __shared__ char smem[];
    const uint32_t sbase = smem_u32(smem);
    const int tid  = threadIdx.x;
    const int wid  = tid >> 5;
    const int lane = tid & 31;
    const int wm   = wid >> 3;   // 0..3  (16-row slice)
    const int wn   = wid & 7;    // 0..7  (32-col slice)
    const int row0 = blockIdx.x * TM;

    int*           sicnt  = (int*)(smem + SM_TBL);
    unsigned char* silist = (unsigned char*)(smem + SM_ILIST);
    float*         sMaxv  = (float*)(smem + SM_MAXV);
    float*         sLsev  = (float*)(smem + SM_LSEV);

    // stage inverse-map tables (covered by first __syncthreads in loop)
    if (tid < NM) sicnt[tid] = g_icnt[tid];
    if (tid < NM * MAXINV) silist[tid] = g_ilist[tid];
    if (tid + 1024 < NM * MAXINV) silist[tid + 1024] = g_ilist[tid + 1024];
    if (tid + 2048 < NM * MAXINV) silist[tid + 2048] = g_ilist[tid + 2048];

    float acc[4][4];
    #pragma unroll
    for (int j = 0; j < 4; j++)
        #pragma unroll
        for (int c = 0; c < 4; c++) acc[j][c] = 0.0f;

    auto issue_chunk = [&](int kc, int buf) {
        // A: 64 rows x 32 floats = 512 float4 (first 512 threads)
        if (tid < 512) {
            int r = tid >> 3, g = tid & 7;
            cp16(sbase + SM_A0 + buf * A_BYTES + (uint32_t)(r * A_PAD + g * 4) * 4,
                 enc + (size_t)(row0 + r) * HD + kc * KC + g * 4);
        }
        // B: 2048 float4, 2 per thread, contiguous
        uint32_t bdst = sbase + SM_B0 + buf * B_BYTES;
        const float* bsrc = g_Bp + (size_t)kc * 8192;
        #pragma unroll
        for (int it = 0; it < 2; it++) {
            int i4 = tid + it * NTHREADS;
            cp16(bdst + (uint32_t)i4 * 16, bsrc + (size_t)i4 * 4);
        }
    };

    auto do_chunk = [&](int buf) {
        const float* sA = (const float*)(smem + SM_A0 + buf * A_BYTES);
        const char*  sB = smem + SM_B0 + buf * B_BYTES;
        #pragma unroll
        for (int ks = 0; ks < 4; ks++) {
            uint32_t afr[4];
            {
                const float* ap = sA + (wm * 16 + (lane >> 2)) * A_PAD
                                     + ks * 8 + (lane & 3);
                afr[0] = __float_as_uint(ap[0]);
                afr[1] = __float_as_uint(ap[8 * A_PAD]);
                afr[2] = __float_as_uint(ap[4]);
                afr[3] = __float_as_uint(ap[8 * A_PAD + 4]);
            }
            float2 bfr[4];
            #pragma unroll
            for (int j = 0; j < 4; j++) {
                int nt = wn * 4 + j;
                bfr[j] = *(const float2*)(sB + ((nt * 4 + ks) * 32 + lane) * 8);
            }
            #pragma unroll
            for (int j = 0; j < 4; j++)
                mma_tf32(acc[j], afr,
                         __float_as_uint(bfr[j].x), __float_as_uint(bfr[j].y));
        }
    };

    issue_chunk(0, 0);
    CP_COMMIT();

    #pragma unroll 1
    for (int kc = 0; kc < NCHUNK; kc++) {
        const int buf = kc & 1;
        CP_WAIT(0);          // chunk kc's data landed
        __syncthreads();     // visible to all; buf^1 free (kc-1's compute done by all)
        if (kc + 1 < NCHUNK) {
            issue_chunk(kc + 1, buf ^ 1);
            CP_COMMIT();
        }
        do_chunk(buf);
    }
    __syncthreads();  // all compute done before aliasing GEMM buffers

    // ---- epilogue ----
    const float scale = 0.039528470752104741f;  // 1/sqrt(640)
    float* sPhone = (float*)(smem + SM_PHONE);
    float* sPh    = (float*)(smem + SM_PH);

    {
        int r = wm * 16 + (lane >> 2);
        #pragma unroll
        for (int j = 0; j < 4; j++) {
            int c = wn * 32 + j * 8 + (lane & 3) * 2;
            float2 v0 = make_float2(acc[j][0] * scale, acc[j][1] * scale);
            float2 v1 = make_float2(acc[j][2] * scale, acc[j][3] * scale);
            *(float2*)(sPhone + r * P_PAD + c)       = v0;
            *(float2*)(sPhone + (r + 8) * P_PAD + c) = v1;
        }
    }
    __syncthreads();

    // gather-max via inverse map: 64 rows x 96 phonemes
    for (int idx = tid; idx < TM * NM; idx += NTHREADS) {
        int r = idx / NM;
        int m = idx - r * NM;
        int cnt = sicnt[m];
        const unsigned char* lst = silist + m * MAXINV;
        float mx = -INFINITY;
        for (int c = 0; c < cnt; c++)
            mx = fmaxf(mx, sPhone[r * P_PAD + lst[c]]);
        sPh[r * M_PAD + m] = mx;
    }
    __syncthreads();

    // per-row max + logsumexp: 4 threads per row (first 256 threads)
    if (tid < 256) {
        int r = tid >> 2;
        int q = tid & 3;
        const float* row = sPh + r * M_PAD;
        float mx = -INFINITY;
        #pragma unroll
        for (int m = q * 24; m < q * 24 + 24; m++) mx = fmaxf(mx, row[m]);
        mx = fmaxf(mx, __shfl_xor_sync(0xffffffffu, mx, 1));
        mx = fmaxf(mx, __shfl_xor_sync(0xffffffffu, mx, 2));
        float s = 0.0f;
        #pragma unroll
        for (int m = q * 24; m < q * 24 + 24; m++) s += expf(row[m] - mx);
        s += __shfl_xor_sync(0xffffffffu, s, 1);
        s += __shfl_xor_sync(0xffffffffu, s, 2);
        if (q == 0) { sMaxv[r] = mx; sLsev[r] = logf(s); }
    }
    __syncthreads();

    // coalesced output
    for (int idx = tid; idx < TM * NM; idx += NTHREADS) {
        int r = idx / NM;
        int m = idx - r * NM;
        out[(size_t)(row0 + r) * NM + m] = sPh[r * M_PAD + m] - sMaxv[r] - sLsev[r];
    }
}

extern "C" void kernel_launch(void* const* d_in, const int* in_sizes, int n_in,
                              void* d_out, int out_size) {
    const float* enc     = (const float*)d_in[0];
    const float* f2p     = (const float*)d_in[1];
    const float* mapping = (const float*)d_in[2];
    float*       out     = (float*)d_out;

    cudaFuncSetAttribute(phon_mma_kernel,
                         cudaFuncAttributeMaxDynamicSharedMemorySize, SM_TOTAL);

    prep_kernel<<<NCHUNK + 12, 256>>>(f2p, mapping);
    phon_mma_kernel<<<NROWS / TM, NTHREADS, SM_TOTAL>>>(enc, out);
}

// round 10
// speedup vs baseline: 1.5464x; 1.0588x over previous
#include <cuda_runtime.h>
#include <math.h>
#include <stdint.h>

#define NROWS 8192      // B*T
#define HD    640
#define NP    230
#define NM    96
#define TM    64        // rows per CTA
#define KC    32        // k per chunk
#define NCHUNK (HD / KC)  // 20
#define A_PAD 36
#define P_PAD 258
#define M_PAD 97
#define MAXINV 32
#define NTHREADS 512

#define A_BYTES 9216    // 64*36*4
#define B_BYTES 32768   // 8192 floats

// ---- smem byte offsets ----
#define SM_A0    0                        // 2 x 9216  = 18432
#define SM_B0    18432                    // 2 x 32768 -> 83968
// epilogue aliases GEMM region:
#define SM_PHONE 0                        // 64*258*4 = 66048
#define SM_PH    66048                    // 64*97*4  = 24832 -> 90880
// persistent tables:
#define SM_TBL   90880                    // icnt 96*4 -> 91264
#define SM_ILIST 91264                    // 96*32    -> 94336
#define SM_MAXV  94336                    // 64*4
#define SM_LSEV  94592                    // 64*4
#define SM_TOTAL 94848

__device__ float         g_Bp[NCHUNK * 8192];   // fragment-permuted B (tf32-rounded)
__device__ int           g_icnt[NM];
__device__ unsigned char g_ilist[NM * MAXINV];

// ---------------- helpers ----------------
__device__ __forceinline__ uint32_t smem_u32(const void* p) {
    uint32_t a;
    asm("{ .reg .u64 t; cvta.to.shared.u64 t, %1; cvt.u32.u64 %0, t; }" : "=r"(a) : "l"(p));
    return a;
}
__device__ __forceinline__ void cp16(uint32_t dst, const void* src) {
    asm volatile("cp.async.cg.shared.global [%0], [%1], 16;" :: "r"(dst), "l"(src));
}
#define CP_COMMIT() asm volatile("cp.async.commit_group;" ::: "memory")
#define CP_WAIT(N)  asm volatile("cp.async.wait_group %0;" :: "n"(N) : "memory")

// m16n8k8 tf32 MMA, D += A*B
__device__ __forceinline__ void mma_tf32(float* d, const uint32_t* a, uint32_t b0, uint32_t b1) {
    asm volatile(
        "mma.sync.aligned.m16n8k8.row.col.f32.tf32.tf32.f32 "
        "{%0,%1,%2,%3}, {%4,%5,%6,%7}, {%8,%9}, {%0,%1,%2,%3};"
        : "+f"(d[0]), "+f"(d[1]), "+f"(d[2]), "+f"(d[3])
        : "r"(a[0]), "r"(a[1]), "r"(a[2]), "r"(a[3]), "r"(b0), "r"(b1));
}

// ---------------- prologue kernel ----------------
// blocks 0..19: pack one 32-row chunk of B into fragment order via coalesced smem staging.
// blocks 20..31: inverse map, ONE phoneme per warp, rounds prefetched (MLP=8).
__global__ void prep_kernel(const float* __restrict__ f2p,
                            const float* __restrict__ mapping) {
    __shared__ float s[32 * 232];
    const int tid = threadIdx.x;
    const int b   = blockIdx.x;
    if (b < NCHUNK) {
        const float* src = f2p + (size_t)b * KC * NP;
        for (int idx = tid; idx < KC * NP; idx += 256) {
            int rr = idx / NP, c = idx - rr * NP;
            s[rr * 232 + c] = src[idx];
        }
        __syncthreads();
        float* dst = g_Bp + (size_t)b * 8192;
        for (int rem = tid; rem < 8192; rem += 256) {
            int nt   = rem >> 8;
            int r2   = rem & 255;
            int ks   = r2 >> 6;
            int lane = (r2 >> 1) & 31;
            int i    = r2 & 1;
            int n  = nt * 8 + (lane >> 2);
            int kk = ks * 8 + (lane & 3) + 4 * i;
            float v = (n < NP) ? s[kk * 232 + n] : 0.0f;
            uint32_t t;
            asm("cvt.rna.tf32.f32 %0, %1;" : "=r"(t) : "f"(v));
            dst[rem] = __uint_as_float(t);
        }
    } else {
        int wid  = tid >> 5;
        int lane = tid & 31;
        int m = (b - NCHUNK) * 8 + wid;   // 0..95, one phoneme per warp
        bool hit[8];
        #pragma unroll
        for (int rr = 0; rr < 8; rr++) {
            int p = rr * 32 + lane;
            hit[rr] = (p < NP) && (mapping[m * NP + p] > 0.0f);  // independent loads
        }
        int cnt = 0;
        #pragma unroll
        for (int rr = 0; rr < 8; rr++) {
            unsigned bal = __ballot_sync(0xffffffffu, hit[rr]);
            if (hit[rr]) {
                int pos = cnt + __popc(bal & ((1u << lane) - 1u));
                if (pos < MAXINV) g_ilist[m * MAXINV + pos] = (unsigned char)(rr * 32 + lane);
            }
            cnt += __popc(bal);
        }
        if (lane == 0) g_icnt[m] = (cnt < MAXINV) ? cnt : MAXINV;
    }
}

// ---------------- main kernel ----------------
// 512 threads = 16 warps in a 2 x 8 grid; warp tile 32 x 32.
__global__ __launch_bounds__(NTHREADS, 1)
void phon_mma_kernel(const float* __restrict__ enc, float* __restrict__ out) {
    extern __shared__ char smem[];
    const uint32_t sbase = smem_u32(smem);
    const int tid  = threadIdx.x;
    const int wid  = tid >> 5;
    const int lane = tid & 31;
    const int wm   = wid >> 3;   // 0..1  (32-row slice)
    const int wn   = wid & 7;    // 0..7  (32-col slice)
    const int row0 = blockIdx.x * TM;

    int*           sicnt  = (int*)(smem + SM_TBL);
    unsigned char* silist = (unsigned char*)(smem + SM_ILIST);
    float*         sMaxv  = (float*)(smem + SM_MAXV);
    float*         sLsev  = (float*)(smem + SM_LSEV);

    // stage inverse-map tables (covered by first __syncthreads in loop)
    if (tid < NM) sicnt[tid] = g_icnt[tid];
    for (int i = tid; i < NM * MAXINV; i += NTHREADS) silist[i] = g_ilist[i];

    float acc[2][4][4];
    #pragma unroll
    for (int i = 0; i < 2; i++)
        #pragma unroll
        for (int j = 0; j < 4; j++)
            #pragma unroll
            for (int c = 0; c < 4; c++) acc[i][j][c] = 0.0f;

    auto issue_chunk = [&](int kc, int buf) {
        // A: 64 rows x 32 floats = 512 float4, one per thread
        {
            int r = tid >> 3, g = tid & 7;
            cp16(sbase + SM_A0 + buf * A_BYTES + (uint32_t)(r * A_PAD + g * 4) * 4,
                 enc + (size_t)(row0 + r) * HD + kc * KC + g * 4);
        }
        // B: 2048 float4, 4 per thread, contiguous
        uint32_t bdst = sbase + SM_B0 + buf * B_BYTES;
        const float* bsrc = g_Bp + (size_t)kc * 8192;
        #pragma unroll
        for (int it = 0; it < 4; it++) {
            int i4 = tid + it * NTHREADS;
            cp16(bdst + (uint32_t)i4 * 16, bsrc + (size_t)i4 * 4);
        }
    };

    auto do_chunk = [&](int buf) {
        const float* sA = (const float*)(smem + SM_A0 + buf * A_BYTES);
        const char*  sB = smem + SM_B0 + buf * B_BYTES;

        uint32_t afr[2][2][4];   // [slot][i][reg]
        float2   bfr[2][4];      // [slot][j]

        auto load_frag = [&](int ks, int slot) {
            #pragma unroll
            for (int i = 0; i < 2; i++) {
                const float* ap = sA + (wm * 32 + i * 16 + (lane >> 2)) * A_PAD
                                     + ks * 8 + (lane & 3);
                afr[slot][i][0] = __float_as_uint(ap[0]);
                afr[slot][i][1] = __float_as_uint(ap[8 * A_PAD]);
                afr[slot][i][2] = __float_as_uint(ap[4]);
                afr[slot][i][3] = __float_as_uint(ap[8 * A_PAD + 4]);
            }
            #pragma unroll
            for (int j = 0; j < 4; j++) {
                int nt = wn * 4 + j;
                bfr[slot][j] = *(const float2*)(sB + ((nt * 4 + ks) * 32 + lane) * 8);
            }
        };

        load_frag(0, 0);
        #pragma unroll
        for (int ks = 0; ks < 4; ks++) {
            const int cur = ks & 1;
            if (ks < 3) load_frag(ks + 1, cur ^ 1);   // prefetch next ks before MMAs
            #pragma unroll
            for (int i = 0; i < 2; i++)
                #pragma unroll
                for (int j = 0; j < 4; j++)
                    mma_tf32(acc[i][j], afr[cur][i],
                             __float_as_uint(bfr[cur][j].x),
                             __float_as_uint(bfr[cur][j].y));
        }
    };

    issue_chunk(0, 0);
    CP_COMMIT();

    #pragma unroll 1
    for (int kc = 0; kc < NCHUNK; kc++) {
        const int buf = kc & 1;
        CP_WAIT(0);          // chunk kc's data landed
        __syncthreads();     // visible to all; buf^1 free (kc-1 compute done by all)
        if (kc + 1 < NCHUNK) {
            issue_chunk(kc + 1, buf ^ 1);
            CP_COMMIT();
        }
        do_chunk(buf);
    }
    __syncthreads();  // all compute done before aliasing GEMM buffers

    // ---- epilogue ----
    const float scale = 0.039528470752104741f;  // 1/sqrt(640)
    float* sPhone = (float*)(smem + SM_PHONE);
    float* sPh    = (float*)(smem + SM_PH);

    #pragma unroll
    for (int i = 0; i < 2; i++) {
        int r = wm * 32 + i * 16 + (lane >> 2);
        #pragma unroll
        for (int j = 0; j < 4; j++) {
            int c = wn * 32 + j * 8 + (lane & 3) * 2;
            float2 v0 = make_float2(acc[i][j][0] * scale, acc[i][j][1] * scale);
            float2 v1 = make_float2(acc[i][j][2] * scale, acc[i][j][3] * scale);
            *(float2*)(sPhone + r * P_PAD + c)       = v0;
            *(float2*)(sPhone + (r + 8) * P_PAD + c) = v1;
        }
    }
    __syncthreads();

    // gather-max via inverse map: 64 rows x 96 phonemes
    for (int idx = tid; idx < TM * NM; idx += NTHREADS) {
        int r = idx / NM;
        int m = idx - r * NM;
        int cnt = sicnt[m];
        const unsigned char* lst = silist + m * MAXINV;
        float mx = -INFINITY;
        for (int c = 0; c < cnt; c++)
            mx = fmaxf(mx, sPhone[r * P_PAD + lst[c]]);
        sPh[r * M_PAD + m] = mx;
    }
    __syncthreads();

    // per-row max + logsumexp: 4 threads per row (first 256 threads)
    if (tid < 256) {
        int r = tid >> 2;
        int q = tid & 3;
        const float* row = sPh + r * M_PAD;
        float mx = -INFINITY;
        #pragma unroll
        for (int m = q * 24; m < q * 24 + 24; m++) mx = fmaxf(mx, row[m]);
        mx = fmaxf(mx, __shfl_xor_sync(0xffffffffu, mx, 1));
        mx = fmaxf(mx, __shfl_xor_sync(0xffffffffu, mx, 2));
        float s = 0.0f;
        #pragma unroll
        for (int m = q * 24; m < q * 24 + 24; m++) s += expf(row[m] - mx);
        s += __shfl_xor_sync(0xffffffffu, s, 1);
        s += __shfl_xor_sync(0xffffffffu, s, 2);
        if (q == 0) { sMaxv[r] = mx; sLsev[r] = logf(s); }
    }
    __syncthreads();

    // coalesced output
    for (int idx = tid; idx < TM * NM; idx += NTHREADS) {
        int r = idx / NM;
        int m = idx - r * NM;
        out[(size_t)(row0 + r) * NM + m] = sPh[r * M_PAD + m] - sMaxv[r] - sLsev[r];
    }
}

extern "C" void kernel_launch(void* const* d_in, const int* in_sizes, int n_in,
                              void* d_out, int out_size) {
    const float* enc     = (const float*)d_in[0];
    const float* f2p     = (const float*)d_in[1];
    const float* mapping = (const float*)d_in[2];
    float*       out     = (float*)d_out;

    cudaFuncSetAttribute(phon_mma_kernel,
                         cudaFuncAttributeMaxDynamicSharedMemorySize, SM_TOTAL);

    prep_kernel<<<NCHUNK + 12, 256>>>(f2p, mapping);
    phon_mma_kernel<<<NROWS / TM, NTHREADS, SM_TOTAL>>>(enc, out);
}

// round 11
// speedup vs baseline: 1.7106x; 1.1062x over previous
#include <cuda_runtime.h>
#include <math.h>
#include <stdint.h>

#define NROWS 8192      // B*T
#define HD    640
#define NP    230
#define NM    96
#define TM    64        // rows per CTA
#define KC    32        // k per chunk
#define NCHUNK (HD / KC)  // 20
#define ASTRIDE 644     // floats per A row in smem; 644 % 32 == 4 -> conflict-free frags
#define P_PAD 258
#define M_PAD 97
#define MAXINV 32
#define NTHREADS 512

// ---- smem byte offsets ----
// A tile: 64 rows x ASTRIDE floats = 164864 bytes, loaded ONCE.
// epilogue aliases the A region:
#define SM_PHONE 0                        // 64*258*4 = 66048
#define SM_PH    66048                    // 64*97*4  = 24832 -> 90880 (< 164864)
// persistent tables (beyond A region):
#define SM_TBL   164864                   // icnt 96*4 -> 165248
#define SM_ILIST 165248                   // 96*32    -> 168320
#define SM_MAXV  168320                   // 64*4
#define SM_LSEV  168576                   // 64*4
#define SM_TOTAL 168832

__device__ float         g_Bp[NCHUNK * 8192];   // fragment-permuted B (tf32-rounded)
__device__ int           g_icnt[NM];
__device__ unsigned char g_ilist[NM * MAXINV];

// ---------------- helpers ----------------
__device__ __forceinline__ uint32_t smem_u32(const void* p) {
    uint32_t a;
    asm("{ .reg .u64 t; cvta.to.shared.u64 t, %1; cvt.u32.u64 %0, t; }" : "=r"(a) : "l"(p));
    return a;
}
__device__ __forceinline__ void cp16(uint32_t dst, const void* src) {
    asm volatile("cp.async.cg.shared.global [%0], [%1], 16;" :: "r"(dst), "l"(src));
}
#define CP_COMMIT() asm volatile("cp.async.commit_group;" ::: "memory")
#define CP_WAIT(N)  asm volatile("cp.async.wait_group %0;" :: "n"(N) : "memory")

// m16n8k8 tf32 MMA, D += A*B
__device__ __forceinline__ void mma_tf32(float* d, const uint32_t* a, uint32_t b0, uint32_t b1) {
    asm volatile(
        "mma.sync.aligned.m16n8k8.row.col.f32.tf32.tf32.f32 "
        "{%0,%1,%2,%3}, {%4,%5,%6,%7}, {%8,%9}, {%0,%1,%2,%3};"
        : "+f"(d[0]), "+f"(d[1]), "+f"(d[2]), "+f"(d[3])
        : "r"(a[0]), "r"(a[1]), "r"(a[2]), "r"(a[3]), "r"(b0), "r"(b1));
}

// ---------------- prologue kernel ----------------
// blocks 0..19: pack one 32-row chunk of B into fragment order via coalesced smem staging.
// blocks 20..31: inverse map, ONE phoneme per warp, rounds prefetched (MLP=8).
__global__ void prep_kernel(const float* __restrict__ f2p,
                            const float* __restrict__ mapping) {
    __shared__ float s[32 * 232];
    const int tid = threadIdx.x;
    const int b   = blockIdx.x;
    if (b < NCHUNK) {
        const float* src = f2p + (size_t)b * KC * NP;
        for (int idx = tid; idx < KC * NP; idx += 256) {
            int rr = idx / NP, c = idx - rr * NP;
            s[rr * 232 + c] = src[idx];
        }
        __syncthreads();
        float* dst = g_Bp + (size_t)b * 8192;
        for (int rem = tid; rem < 8192; rem += 256) {
            int nt   = rem >> 8;
            int r2   = rem & 255;
            int ks   = r2 >> 6;
            int lane = (r2 >> 1) & 31;
            int i    = r2 & 1;
            int n  = nt * 8 + (lane >> 2);
            int kk = ks * 8 + (lane & 3) + 4 * i;
            float v = (n < NP) ? s[kk * 232 + n] : 0.0f;
            uint32_t t;
            asm("cvt.rna.tf32.f32 %0, %1;" : "=r"(t) : "f"(v));
            dst[rem] = __uint_as_float(t);
        }
    } else {
        int wid  = tid >> 5;
        int lane = tid & 31;
        int m = (b - NCHUNK) * 8 + wid;   // 0..95, one phoneme per warp
        bool hit[8];
        #pragma unroll
        for (int rr = 0; rr < 8; rr++) {
            int p = rr * 32 + lane;
            hit[rr] = (p < NP) && (mapping[m * NP + p] > 0.0f);  // independent loads
        }
        int cnt = 0;
        #pragma unroll
        for (int rr = 0; rr < 8; rr++) {
            unsigned bal = __ballot_sync(0xffffffffu, hit[rr]);
            if (hit[rr]) {
                int pos = cnt + __popc(bal & ((1u << lane) - 1u));
                if (pos < MAXINV) g_ilist[m * MAXINV + pos] = (unsigned char)(rr * 32 + lane);
            }
            cnt += __popc(bal);
        }
        if (lane == 0) g_icnt[m] = (cnt < MAXINV) ? cnt : MAXINV;
    }
}

// ---------------- main kernel ----------------
// 512 threads = 16 warps (2 x 8); warp tile 32 x 32.
// A tile resident in smem for all 20 chunks; B fragments streamed via LDG (L2-resident).
// NO barriers and NO async-waits in the mainloop.
__global__ __launch_bounds__(NTHREADS, 1)
void phon_mma_kernel(const float* __restrict__ enc, float* __restrict__ out) {
    extern __shared__ char smem[];
    const uint32_t sbase = smem_u32(smem);
    const int tid  = threadIdx.x;
    const int wid  = tid >> 5;
    const int lane = tid & 31;
    const int wm   = wid >> 3;   // 0..1  (32-row slice)
    const int wn   = wid & 7;    // 0..7  (32-col slice)
    const int row0 = blockIdx.x * TM;

    int*           sicnt  = (int*)(smem + SM_TBL);
    unsigned char* silist = (unsigned char*)(smem + SM_ILIST);
    float*         sMaxv  = (float*)(smem + SM_MAXV);
    float*         sLsev  = (float*)(smem + SM_LSEV);

    // stage inverse-map tables
    if (tid < NM) sicnt[tid] = g_icnt[tid];
    for (int i = tid; i < NM * MAXINV; i += NTHREADS) silist[i] = g_ilist[i];

    // stage the ENTIRE A tile: 64 rows x 640 floats = 10240 float4, 20 per thread
    #pragma unroll
    for (int it = 0; it < 20; it++) {
        int idx = tid + it * NTHREADS;
        int r = idx / 160;           // 160 float4 per row
        int g = idx - r * 160;
        cp16(sbase + (uint32_t)(r * ASTRIDE + g * 4) * 4,
             enc + (size_t)(row0 + r) * HD + g * 4);
    }
    CP_COMMIT();
    CP_WAIT(0);
    __syncthreads();   // A tile + tables visible to all warps

    const float* sA = (const float*)smem;

    float acc[2][4][4];
    #pragma unroll
    for (int i = 0; i < 2; i++)
        #pragma unroll
        for (int j = 0; j < 4; j++)
            #pragma unroll
            for (int c = 0; c < 4; c++) acc[i][j][c] = 0.0f;

    // mainloop: zero synchronization
    #pragma unroll 1
    for (int kc = 0; kc < NCHUNK; kc++) {
        // all 16 B fragments for this chunk: coalesced LDG.64 from L2-resident g_Bp
        const float* bch = g_Bp + (size_t)kc * 8192;
        float2 bfr[4][4];   // [ks][j]
        #pragma unroll
        for (int j = 0; j < 4; j++)
            #pragma unroll
            for (int ks = 0; ks < 4; ks++)
                bfr[ks][j] = __ldg((const float2*)(bch + ((wn * 4 + j) * 4 + ks) * 64 + lane * 2));

        const int kbase = kc * KC;
        #pragma unroll
        for (int ks = 0; ks < 4; ks++) {
            uint32_t afr[2][4];
            #pragma unroll
            for (int i = 0; i < 2; i++) {
                const float* ap = sA + (wm * 32 + i * 16 + (lane >> 2)) * ASTRIDE
                                     + kbase + ks * 8 + (lane & 3);
                afr[i][0] = __float_as_uint(ap[0]);
                afr[i][1] = __float_as_uint(ap[8 * ASTRIDE]);
                afr[i][2] = __float_as_uint(ap[4]);
                afr[i][3] = __float_as_uint(ap[8 * ASTRIDE + 4]);
            }
            #pragma unroll
            for (int i = 0; i < 2; i++)
                #pragma unroll
                for (int j = 0; j < 4; j++)
                    mma_tf32(acc[i][j], afr[i],
                             __float_as_uint(bfr[ks][j].x),
                             __float_as_uint(bfr[ks][j].y));
        }
    }
    __syncthreads();   // all warps done reading sA before epilogue aliases it

    // ---- epilogue ----
    const float scale = 0.039528470752104741f;  // 1/sqrt(640)
    float* sPhone = (float*)(smem + SM_PHONE);
    float* sPh    = (float*)(smem + SM_PH);

    #pragma unroll
    for (int i = 0; i < 2; i++) {
        int r = wm * 32 + i * 16 + (lane >> 2);
        #pragma unroll
        for (int j = 0; j < 4; j++) {
            int c = wn * 32 + j * 8 + (lane & 3) * 2;
            float2 v0 = make_float2(acc[i][j][0] * scale, acc[i][j][1] * scale);
            float2 v1 = make_float2(acc[i][j][2] * scale, acc[i][j][3] * scale);
            *(float2*)(sPhone + r * P_PAD + c)       = v0;
            *(float2*)(sPhone + (r + 8) * P_PAD + c) = v1;
        }
    }
    __syncthreads();

    // gather-max via inverse map: 64 rows x 96 phonemes
    for (int idx = tid; idx < TM * NM; idx += NTHREADS) {
        int r = idx / NM;
        int m = idx - r * NM;
        int cnt = sicnt[m];
        const unsigned char* lst = silist + m * MAXINV;
        float mx = -INFINITY;
        for (int c = 0; c < cnt; c++)
            mx = fmaxf(mx, sPhone[r * P_PAD + lst[c]]);
        sPh[r * M_PAD + m] = mx;
    }
    __syncthreads();

    // per-row max + logsumexp: 4 threads per row (first 256 threads)
    if (tid < 256) {
        int r = tid >> 2;
        int q = tid & 3;
        const float* row = sPh + r * M_PAD;
        float mx = -INFINITY;
        #pragma unroll
        for (int m = q * 24; m < q * 24 + 24; m++) mx = fmaxf(mx, row[m]);
        mx = fmaxf(mx, __shfl_xor_sync(0xffffffffu, mx, 1));
        mx = fmaxf(mx, __shfl_xor_sync(0xffffffffu, mx, 2));
        float s = 0.0f;
        #pragma unroll
        for (int m = q * 24; m < q * 24 + 24; m++) s += expf(row[m] - mx);
        s += __shfl_xor_sync(0xffffffffu, s, 1);
        s += __shfl_xor_sync(0xffffffffu, s, 2);
        if (q == 0) { sMaxv[r] = mx; sLsev[r] = logf(s); }
    }
    __syncthreads();

    // coalesced output
    for (int idx = tid; idx < TM * NM; idx += NTHREADS) {
        int r = idx / NM;
        int m = idx - r * NM;
        out[(size_t)(row0 + r) * NM + m] = sPh[r * M_PAD + m] - sMaxv[r] - sLsev[r];
    }
}

extern "C" void kernel_launch(void* const* d_in, const int* in_sizes, int n_in,
                              void* d_out, int out_size) {
    const float* enc     = (const float*)d_in[0];
    const float* f2p     = (const float*)d_in[1];
    const float* mapping = (const float*)d_in[2];
    float*       out     = (float*)d_out;

    cudaFuncSetAttribute(phon_mma_kernel,
                         cudaFuncAttributeMaxDynamicSharedMemorySize, SM_TOTAL);

    prep_kernel<<<NCHUNK + 12, 256>>>(f2p, mapping);
    phon_mma_kernel<<<NROWS / TM, NTHREADS, SM_TOTAL>>>(enc, out);
}